// round 3
// baseline (speedup 1.0000x reference)
#include <cuda_runtime.h>
#include <cuda_bf16.h>

// Problem constants (fixed shapes from setup_inputs)
#define B_DIM 8
#define T_DIM 4096
#define D_DIM 1024
#define K_FFT 64
#define F_DIM (K_FFT / 2 + 1)        // 33

#define CONV_BLOCKS (B_DIM * (D_DIM / 64))   // 128
#define GRID_TOTAL  888                      // 6 blocks/SM * 148 SMs: one exact wave
#define ZBLOCKS     (GRID_TOTAL - CONV_BLOCKS)  // 760

// ---------------------------------------------------------------------------
// Fused kernel:
//   blocks [0, CONV_BLOCKS): per-(batch, 64-channel tile) filter build +
//       circular convolution of the last K_FFT timesteps.
//   blocks [CONV_BLOCKS, GRID_TOTAL): zero-fill of rows [0, T-K) per batch.
// Sized for 6 resident blocks/SM (<=42 regs, ~33 KB smem) so the store path
// has 48 warps/SM and there is no straggler wave.
// ---------------------------------------------------------------------------
__global__ void __launch_bounds__(256, 6) spectral_fused_kernel(
    const float* __restrict__ x, const float* __restrict__ mask,
    const float* __restrict__ mix_w, float* __restrict__ out)
{
    __shared__ float ws[K_FFT * 64];          // 16KB: first g-staging, then window [k][dl]
    __shared__ float f_sh[64 * (K_FFT + 1)];  // 16.6KB: filter [dl][n], pad 65
    __shared__ float tab[K_FFT];              // cos(2*pi*n/64)
    __shared__ float mw_sh[64];               // mix_w tile

    const int bid = blockIdx.x;
    const int tid = threadIdx.x;

    if (bid >= CONV_BLOCKS) {
        // ---- zero path: rows [0, T-K) of every batch ----
        const int z4b = (T_DIM - K_FFT) * D_DIM / 4;       // 1032192 float4 per batch
        const int zstride = ZBLOCKS * 256;                 // 194560
        const int i0 = (bid - CONV_BLOCKS) * 256 + tid;
        const float4 z = make_float4(0.f, 0.f, 0.f, 0.f);
        float4* __restrict__ o4 = (float4*)out;

        #pragma unroll
        for (int b = 0; b < B_DIM; b++) {
            float4* __restrict__ ob = o4 + (long long)b * (T_DIM * D_DIM / 4);
            for (int i = i0; i < z4b; i += zstride)
                ob[i] = z;
        }
        return;
    }

    // ---- conv path ----
    const int b  = bid >> 4;          // 0..7
    const int d0 = (bid & 15) * 64;   // channel tile base

    // Prefetch the window into registers (hides global latency behind build).
    const float* xb = x + ((long long)b * T_DIM + (T_DIM - K_FFT)) * D_DIM + d0;
    float xv[16];
    #pragma unroll
    for (int i = 0; i < 16; i++) {
        int idx = tid + i * 256;
        xv[i] = xb[(long long)(idx >> 6) * D_DIM + (idx & 63)];
    }

    // Stage sigmoid(mask) tile (2112 floats) into ws, plus twiddles and mix_w.
    const float* mrow = mask + (long long)d0 * F_DIM;
    for (int idx = tid; idx < 64 * F_DIM; idx += 256)
        ws[idx] = 1.0f / (1.0f + expf(-mrow[idx]));
    if (tid < K_FFT)
        tab[tid] = cospif((float)tid * (1.0f / 32.0f));   // exact twiddles
    if (tid < 64)
        mw_sh[tid] = mix_w[d0 + tid];
    __syncthreads();

    // Build time-domain filter: f[dl][n] = mix_w/64 *
    //   ( g0 + 2*sum_{f=1..31} g_f cos(2 pi f n / 64) + g32 * (-1)^n )
    // Lane mapping: n = idx&63 (consecutive per lane), dl = idx>>6 (warp-uniform)
    // -> g reads are warp broadcasts, f_sh writes are bank-conflict-free.
    #pragma unroll
    for (int i = 0; i < 16; i++) {
        int idx = tid + i * 256;
        int n = idx & 63, dl = idx >> 6;
        const float* gd = ws + dl * F_DIM;
        float s = gd[0] + gd[32] * tab[(32 * n) & 63];
        #pragma unroll
        for (int f = 1; f < 32; f++)
            s += 2.0f * gd[f] * tab[(f * n) & 63];
        f_sh[dl * 65 + n] = s * (1.0f / 64.0f) * mw_sh[dl];
    }
    __syncthreads();

    // Overwrite ws with the window [k][dl].
    #pragma unroll
    for (int i = 0; i < 16; i++)
        ws[tid + i * 256] = xv[i];
    __syncthreads();

    const int dl = tid & 63;
    const int t0 = (tid >> 6) * 16;   // t-group base

    float acc[16];
    #pragma unroll
    for (int j = 0; j < 16; j++) acc[j] = 0.0f;

    // y[t0+j] = sum_k w[k] * f[(t0+j-k) & 63]; LDS reads conflict-free
    // (addr = dl*65 + c -> bank (dl + c) & 31, lanes have distinct dl).
    const float* frow = f_sh + dl * 65;
    #pragma unroll
    for (int k = 0; k < K_FFT; k++) {
        float wv = ws[k * 64 + dl];
        #pragma unroll
        for (int j = 0; j < 16; j++)
            acc[j] += wv * frow[(t0 + j - k + K_FFT) & 63];
    }

    float* ob = out + ((long long)b * T_DIM + (T_DIM - K_FFT)) * D_DIM + d0;
    #pragma unroll
    for (int j = 0; j < 16; j++)
        ob[(long long)(t0 + j) * D_DIM + dl] = acc[j];
}

// ---------------------------------------------------------------------------
// Launch: one kernel, one graph node.
// ---------------------------------------------------------------------------
extern "C" void kernel_launch(void* const* d_in, const int* in_sizes, int n_in,
                              void* d_out, int out_size)
{
    const float* x     = (const float*)d_in[0];   // (B, T, D) fp32
    const float* mask  = (const float*)d_in[1];   // (D, 33)   fp32
    const float* mix_w = (const float*)d_in[2];   // (D,)      fp32
    float* out = (float*)d_out;                   // (B, T, D) fp32

    spectral_fused_kernel<<<GRID_TOTAL, 256>>>(x, mask, mix_w, out);
}

// round 4
// speedup vs baseline: 1.3337x; 1.3337x over previous
#include <cuda_runtime.h>
#include <cuda_bf16.h>

// Problem constants (fixed shapes from setup_inputs)
#define B_DIM 8
#define T_DIM 4096
#define D_DIM 1024
#define K_FFT 64
#define F_DIM (K_FFT / 2 + 1)        // 33

#define CONV_BLOCKS (B_DIM * (D_DIM / 64))      // 128
#define GRID_TOTAL  592                         // 4 blocks/SM * 148 SMs: ONE exact wave
#define ZBLOCKS     (GRID_TOTAL - CONV_BLOCKS)  // 464

// ---------------------------------------------------------------------------
// Fused kernel (R2 structure, exact-wave grid):
//   blocks [0, CONV_BLOCKS): filter build + register-resident circular conv
//       of the last K_FFT timesteps for one (batch, 64-channel tile).
//   blocks [CONV_BLOCKS, GRID_TOTAL): zero-fill rows [0, T-K) of every batch.
// 4 blocks/SM (64-reg cap), no straggler wave.
// ---------------------------------------------------------------------------
__global__ void __launch_bounds__(256, 4) spectral_fused_kernel(
    const float* __restrict__ x, const float* __restrict__ mask,
    const float* __restrict__ mix_w, float* __restrict__ out)
{
    __shared__ float g_sh[64 * F_DIM];        // sigmoid(mask) tile [dl][f]
    __shared__ float tab[K_FFT];              // cos(2*pi*n/64)
    __shared__ float w_sh[K_FFT * 64];        // window [k][dl]
    __shared__ float f_sh[64 * (K_FFT + 1)];  // filter [dl][n], pad 65

    const int bid = blockIdx.x;
    const int tid = threadIdx.x;

    if (bid >= CONV_BLOCKS) {
        // ---- zero path: rows [0, T-K) of each batch ----
        const long long z4_per_b  = (long long)(T_DIM - K_FFT) * D_DIM / 4; // 1032192
        const long long n4        = z4_per_b * B_DIM;
        const long long b_stride4 = (long long)T_DIM * D_DIM / 4;
        float4* __restrict__ o4 = (float4*)out;
        const float4 z = make_float4(0.f, 0.f, 0.f, 0.f);

        long long i = (long long)(bid - CONV_BLOCKS) * 256 + tid;
        const long long stride = (long long)ZBLOCKS * 256;
        for (; i < n4; i += stride) {
            long long b   = i / z4_per_b;             // const-div -> mulhi
            long long off = i - b * z4_per_b;
            __stcs(&o4[b * b_stride4 + off], z);      // streaming store
        }
        return;
    }

    // ---- conv path ----
    const int b  = bid >> 4;          // 0..7
    const int d0 = (bid & 15) * 64;   // channel tile base

    // Stage sigmoid(mask) for the 64 channels (2112 contiguous floats).
    const float* mrow = mask + (long long)d0 * F_DIM;
    for (int idx = tid; idx < 64 * F_DIM; idx += 256)
        g_sh[idx] = 1.0f / (1.0f + expf(-mrow[idx]));
    if (tid < K_FFT)
        tab[tid] = cospif((float)tid * (1.0f / 32.0f));   // exact twiddles

    // Stage the last-64-timestep window (coalesced).
    const float* xb = x + ((long long)b * T_DIM + (T_DIM - K_FFT)) * D_DIM + d0;
    #pragma unroll
    for (int i = 0; i < 16; i++) {
        int idx = tid + i * 256;
        int k = idx >> 6, dl = idx & 63;
        w_sh[idx] = xb[(long long)k * D_DIM + dl];
    }
    __syncthreads();

    // Build time-domain filter: f[dl][n] = mix_w/64 *
    //   ( g0 + 2*sum_{f=1..31} g_f cos(2 pi f n/64) + g32*(-1)^n )
    #pragma unroll
    for (int i = 0; i < 16; i++) {
        int idx = tid + i * 256;
        int dl = idx >> 6, n = idx & 63;
        const float* gd = g_sh + dl * F_DIM;
        float s = gd[0] + gd[32] * tab[(32 * n) & 63];
        #pragma unroll
        for (int f = 1; f < 32; f++)
            s += 2.0f * gd[f] * tab[(f * n) & 63];
        f_sh[dl * 65 + n] = s * (1.0f / 64.0f) * mix_w[d0 + dl];
    }
    __syncthreads();

    const int dl = tid & 63;
    const int tg = tid >> 6;       // 0..3
    const int t0 = tg * 16;

    // Pre-rotated filter in registers: fr[i] = f[(t0+i)&63]
    //   -> y[t0+j] = sum_k w[k] * fr[(j-k)&63], all compile-time reg indices.
    float fr[K_FFT];
    #pragma unroll
    for (int i = 0; i < K_FFT; i++)
        fr[i] = f_sh[dl * 65 + ((t0 + i) & 63)];

    float acc[16];
    #pragma unroll
    for (int j = 0; j < 16; j++) acc[j] = 0.0f;

    #pragma unroll
    for (int k = 0; k < K_FFT; k++) {
        float wv = w_sh[k * 64 + dl];
        #pragma unroll
        for (int j = 0; j < 16; j++)
            acc[j] += wv * fr[(j - k + K_FFT) & 63];
    }

    float* ob = out + ((long long)b * T_DIM + (T_DIM - K_FFT)) * D_DIM + d0;
    #pragma unroll
    for (int j = 0; j < 16; j++)
        ob[(long long)(t0 + j) * D_DIM + dl] = acc[j];
}

// ---------------------------------------------------------------------------
// Launch: one kernel, one graph node.
// ---------------------------------------------------------------------------
extern "C" void kernel_launch(void* const* d_in, const int* in_sizes, int n_in,
                              void* d_out, int out_size)
{
    const float* x     = (const float*)d_in[0];   // (B, T, D) fp32
    const float* mask  = (const float*)d_in[1];   // (D, 33)   fp32
    const float* mix_w = (const float*)d_in[2];   // (D,)      fp32
    float* out = (float*)d_out;                   // (B, T, D) fp32

    spectral_fused_kernel<<<GRID_TOTAL, 256>>>(x, mask, mix_w, out);
}